// round 3
// baseline (speedup 1.0000x reference)
#include <cuda_runtime.h>
#include <cuda_bf16.h>
#include <cstdint>

// ============================================================================
// BinaryToCost: out[i] = x_i @ Q @ x_i  (x: 1024x2048 {0,1} fp32, Q: 2048^2 fp32)
// Two-level int8 quantized IMMA GEMM:  Q ≈ s*q_hi + (s/254)*q_lo  (s8 each),
// exact int32 accumulation, deterministic integer atomics, scale at the end.
// Uses x^T Q x == x^T Q^T x  => no transpose needed for the B operand.
// ============================================================================

#define NDIM 2048
#define BDIM 1024
#define BM 128
#define BN 128
#define NCHUNK 32          // 16 chunks (k=128 int8) for q_hi + 16 for q_lo
#define NT (NDIM / BN)     // 16
#define MT (BDIM / BM)     // 8
#define STAGE_BYTES 32768  // A(16KB int8) + B(16KB int8)
#define SMEM_BYTES (2 * STAGE_BYTES)

// ---------------------------------------------------------------------------
__device__ __align__(16) int8_t g_xi[BDIM * NDIM];   // 2 MB  x as s8 {0,1}
__device__ __align__(16) int8_t g_qh[NDIM * NDIM];   // 4 MB  hi-level s8 of Q
__device__ __align__(16) int8_t g_ql[NDIM * NDIM];   // 4 MB  lo-level s8 of Q
__device__ int g_acc_hi[BDIM];
__device__ int g_acc_lo[BDIM];
__device__ unsigned g_maxbits;

// ---------------------------------------------------------------------------
__device__ __forceinline__ uint32_t smem_u32(const void* p) {
    return (uint32_t)__cvta_generic_to_shared(p);
}
__device__ __forceinline__ uint32_t sw128(uint32_t off) {
    return off ^ ((off >> 3) & 0x70);
}
__device__ __forceinline__ void cp_async16(uint32_t dst, const void* src) {
    asm volatile("cp.async.cg.shared.global [%0], [%1], 16;"
                 :: "r"(dst), "l"(src) : "memory");
}

#define LDSM_X4(r, addr)                                                      \
    asm volatile("ldmatrix.sync.aligned.m8n8.x4.shared.b16 {%0,%1,%2,%3}, [%4];" \
                 : "=r"((r)[0]), "=r"((r)[1]), "=r"((r)[2]), "=r"((r)[3])     \
                 : "r"(addr))

__device__ __forceinline__ void imma16832(int* d, const uint32_t* a,
                                          const uint32_t* b) {
    asm volatile(
        "mma.sync.aligned.m16n8k32.row.col.s32.s8.s8.s32 "
        "{%0,%1,%2,%3}, {%4,%5,%6,%7}, {%8,%9}, {%0,%1,%2,%3};"
        : "+r"(d[0]), "+r"(d[1]), "+r"(d[2]), "+r"(d[3])
        : "r"(a[0]), "r"(a[1]), "r"(a[2]), "r"(a[3]), "r"(b[0]), "r"(b[1]));
}

__device__ __forceinline__ uint32_t pack4(int a, int b, int c, int d) {
    return (a & 0xff) | ((b & 0xff) << 8) | ((c & 0xff) << 16) |
           ((unsigned)(d & 0xff) << 24);
}

// ---------------------------------------------------------------------------
// Prep kernels
// ---------------------------------------------------------------------------
__global__ void k_zero() {
    int t = threadIdx.x;
    g_acc_hi[t] = 0;
    g_acc_lo[t] = 0;
    if (t == 0) g_maxbits = 0;
}

// max|Q| via bit-pattern atomicMax (monotone for abs-float); deterministic.
__global__ void k_max(const float* __restrict__ Q) {
    const float4* q4 = reinterpret_cast<const float4*>(Q);
    int i = blockIdx.x * blockDim.x + threadIdx.x;
    unsigned mx = 0;
#pragma unroll
    for (int j = 0; j < 4; ++j) {
        float4 v = q4[i + j * 262144];
        mx = max(mx, __float_as_uint(v.x) & 0x7fffffffu);
        mx = max(mx, __float_as_uint(v.y) & 0x7fffffffu);
        mx = max(mx, __float_as_uint(v.z) & 0x7fffffffu);
        mx = max(mx, __float_as_uint(v.w) & 0x7fffffffu);
    }
#pragma unroll
    for (int o = 16; o > 0; o >>= 1)
        mx = max(mx, __shfl_xor_sync(0xFFFFFFFF, mx, o));
    if ((threadIdx.x & 31) == 0) atomicMax(&g_maxbits, mx);
}

__global__ void k_prep_x(const float* __restrict__ x) {
    int i = blockIdx.x * blockDim.x + threadIdx.x;  // 16 elems / thread
    const float4* x4 = reinterpret_cast<const float4*>(x) + i * 4;
    uint32_t w[4];
#pragma unroll
    for (int j = 0; j < 4; ++j) {
        float4 v = x4[j];
        w[j] = pack4(v.x != 0.0f, v.y != 0.0f, v.z != 0.0f, v.w != 0.0f);
    }
    reinterpret_cast<uint4*>(g_xi)[i] = make_uint4(w[0], w[1], w[2], w[3]);
}

// Two-level s8 quantization of Q (no transpose needed).
__global__ void k_prep_q(const float* __restrict__ Q) {
    const float maxv = __uint_as_float(g_maxbits);
    const float s = maxv * (1.0f / 127.0f);
    const float s2 = s * (1.0f / 254.0f);
    const float inv_s = 127.0f / maxv;
    const float inv_s2 = inv_s * 254.0f;

    int i = blockIdx.x * blockDim.x + threadIdx.x;  // 16 elems / thread
    const float4* q4 = reinterpret_cast<const float4*>(Q) + i * 4;
    int hi[16], lo[16];
#pragma unroll
    for (int j = 0; j < 4; ++j) {
        float4 v = q4[j];
        float vv[4] = {v.x, v.y, v.z, v.w};
#pragma unroll
        for (int e = 0; e < 4; ++e) {
            int qh = __float2int_rn(vv[e] * inv_s);
            float r = fmaf((float)-qh, s, vv[e]);
            int ql = __float2int_rn(r * inv_s2);
            hi[j * 4 + e] = qh;
            lo[j * 4 + e] = ql;
        }
    }
    uint4 ph = make_uint4(pack4(hi[0], hi[1], hi[2], hi[3]),
                          pack4(hi[4], hi[5], hi[6], hi[7]),
                          pack4(hi[8], hi[9], hi[10], hi[11]),
                          pack4(hi[12], hi[13], hi[14], hi[15]));
    uint4 pl = make_uint4(pack4(lo[0], lo[1], lo[2], lo[3]),
                          pack4(lo[4], lo[5], lo[6], lo[7]),
                          pack4(lo[8], lo[9], lo[10], lo[11]),
                          pack4(lo[12], lo[13], lo[14], lo[15]));
    reinterpret_cast<uint4*>(g_qh)[i] = ph;
    reinterpret_cast<uint4*>(g_ql)[i] = pl;
}

// ---------------------------------------------------------------------------
// int8 GEMM + fused masked row-reduce.  grid (NT, MT), 256 threads (8 warps).
// Warp tile 64x32 (warps 2M x 4N), per warp 4 m16 x 4 n8 imma tiles, k=32/mma.
// Chunks of k=128 bytes; chunks 0-15 = q_hi, 16-31 = q_lo, int32 accumulators
// folded (with per-row/col x mask) into integer row sums at pass boundaries.
// ---------------------------------------------------------------------------
__global__ void __launch_bounds__(256, 1)
k_gemm(const float* __restrict__ x) {
    extern __shared__ __align__(1024) uint8_t smem[];

    const int tid = threadIdx.x;
    const int wid = tid >> 5;
    const int lane = tid & 31;
    const int n0 = blockIdx.x * BN;
    const int m0 = blockIdx.y * BM;
    const int wm = (wid >> 2) * 64;
    const int wn = (wid & 3) * 32;
    const int grp = lane >> 3;
    const int ri = lane & 7;

    // cp.async staging: 1024 16B-granules per 16KB tile, 4/thread per operand
    int rr[4], cc[4];
#pragma unroll
    for (int i = 0; i < 4; ++i) {
        int g = tid + 256 * i;
        rr[i] = g >> 3;
        cc[i] = g & 7;
    }

    auto stage_load = [&](int c, int buf) {
        uint32_t sa = smem_u32(smem + buf * STAGE_BYTES);
        uint32_t sb = sa + 16384;
        int kb = (c & 15) * 128;
        const int8_t* qs = (c < 16) ? g_qh : g_ql;
#pragma unroll
        for (int i = 0; i < 4; ++i) {
            uint32_t off = sw128((uint32_t)(rr[i] * 128 + cc[i] * 16));
            cp_async16(sa + off, g_xi + (m0 + rr[i]) * NDIM + kb + cc[i] * 16);
            cp_async16(sb + off, qs + (n0 + rr[i]) * NDIM + kb + cc[i] * 16);
        }
        asm volatile("cp.async.commit_group;" ::: "memory");
    };

    int cfrag[4][4][4];
#pragma unroll
    for (int mt = 0; mt < 4; ++mt)
#pragma unroll
        for (int nt = 0; nt < 4; ++nt)
#pragma unroll
            for (int r = 0; r < 4; ++r) cfrag[mt][nt][r] = 0;

    int rs_hi0[4] = {0, 0, 0, 0}, rs_hi1[4] = {0, 0, 0, 0};
    int rs_lo0[4] = {0, 0, 0, 0}, rs_lo1[4] = {0, 0, 0, 0};

    // Fold cfrag into masked int row sums, then clear cfrag.
    auto fold = [&](int* r0s, int* r1s) {
#pragma unroll
        for (int mt = 0; mt < 4; ++mt) {
            const float* xp0 =
                x + (m0 + wm + mt * 16 + (lane >> 2)) * NDIM + n0 + wn + (lane & 3) * 2;
            const float* xp1 = xp0 + 8 * NDIM;
            int a0 = 0, a1 = 0;
#pragma unroll
            for (int nt = 0; nt < 4; ++nt) {
                float2 v0 = *reinterpret_cast<const float2*>(xp0 + nt * 8);
                float2 v1 = *reinterpret_cast<const float2*>(xp1 + nt * 8);
                if (v0.x != 0.0f) a0 += cfrag[mt][nt][0];
                if (v0.y != 0.0f) a0 += cfrag[mt][nt][1];
                if (v1.x != 0.0f) a1 += cfrag[mt][nt][2];
                if (v1.y != 0.0f) a1 += cfrag[mt][nt][3];
#pragma unroll
                for (int r = 0; r < 4; ++r) cfrag[mt][nt][r] = 0;
            }
            r0s[mt] += a0;
            r1s[mt] += a1;
        }
    };

    stage_load(0, 0);
    stage_load(1, 1);

    for (int ch = 0; ch < NCHUNK; ++ch) {
        if (ch == NCHUNK - 1)
            asm volatile("cp.async.wait_group 0;" ::: "memory");
        else
            asm volatile("cp.async.wait_group 1;" ::: "memory");
        __syncthreads();

        const int buf = ch & 1;
        const uint32_t sa = smem_u32(smem + buf * STAGE_BYTES);
        const uint32_t sb = sa + 16384;

#pragma unroll
        for (int s = 0; s < 4; ++s) {   // 4 k32-steps per 128B chunk
            const int kb = s * 32;      // byte offset within row
            uint32_t a[4][4];
#pragma unroll
            for (int mt = 0; mt < 4; ++mt) {
                int row = wm + mt * 16 + (grp & 1) * 8 + ri;
                uint32_t addr = sa + sw128((uint32_t)(row * 128 + kb + (grp >> 1) * 16));
                LDSM_X4(a[mt], addr);
            }
            uint32_t b[2][4];
#pragma unroll
            for (int nt2 = 0; nt2 < 2; ++nt2) {
                int row = wn + nt2 * 16 + (grp >> 1) * 8 + ri;
                uint32_t addr = sb + sw128((uint32_t)(row * 128 + kb + (grp & 1) * 16));
                LDSM_X4(b[nt2], addr);
            }
#pragma unroll
            for (int mt = 0; mt < 4; ++mt)
#pragma unroll
                for (int nt = 0; nt < 4; ++nt)
                    imma16832(cfrag[mt][nt], a[mt], &b[nt >> 1][(nt & 1) * 2]);
        }

        __syncthreads();
        if (ch + 2 < NCHUNK) stage_load(ch + 2, buf);

        if (ch == 15) fold(rs_hi0, rs_hi1);
        if (ch == NCHUNK - 1) fold(rs_lo0, rs_lo1);
    }

    // Reduce across the 4 lanes of each row group; leaders atomically add
    // (integer atomics: exact & order-independent => deterministic).
#pragma unroll
    for (int mt = 0; mt < 4; ++mt) {
#pragma unroll
        for (int o = 1; o <= 2; o <<= 1) {
            rs_hi0[mt] += __shfl_xor_sync(0xFFFFFFFF, rs_hi0[mt], o);
            rs_hi1[mt] += __shfl_xor_sync(0xFFFFFFFF, rs_hi1[mt], o);
            rs_lo0[mt] += __shfl_xor_sync(0xFFFFFFFF, rs_lo0[mt], o);
            rs_lo1[mt] += __shfl_xor_sync(0xFFFFFFFF, rs_lo1[mt], o);
        }
    }
    if ((lane & 3) == 0) {
#pragma unroll
        for (int mt = 0; mt < 4; ++mt) {
            int row = m0 + wm + mt * 16 + (lane >> 2);
            atomicAdd(&g_acc_hi[row], rs_hi0[mt]);
            atomicAdd(&g_acc_hi[row + 8], rs_hi1[mt]);
            atomicAdd(&g_acc_lo[row], rs_lo0[mt]);
            atomicAdd(&g_acc_lo[row + 8], rs_lo1[mt]);
        }
    }
}

// Apply scales: out = s*hi + (s/254)*lo
__global__ void k_finish(float* __restrict__ out) {
    const float maxv = __uint_as_float(g_maxbits);
    const float s = maxv * (1.0f / 127.0f);
    const float s2 = s * (1.0f / 254.0f);
    int m = blockIdx.x * blockDim.x + threadIdx.x;
    out[m] = s * (float)g_acc_hi[m] + s2 * (float)g_acc_lo[m];
}

// ---------------------------------------------------------------------------
extern "C" void kernel_launch(void* const* d_in, const int* in_sizes, int n_in,
                              void* d_out, int out_size) {
    const float* x = (const float*)d_in[0];  // [1024, 2048]
    const float* Q = (const float*)d_in[1];  // [2048, 2048]
    float* out = (float*)d_out;              // [1024]

    static bool attr_set = false;
    if (!attr_set) {
        cudaFuncSetAttribute(k_gemm, cudaFuncAttributeMaxDynamicSharedMemorySize,
                             SMEM_BYTES);
        attr_set = true;
    }

    k_zero<<<1, BDIM>>>();
    k_max<<<1024, 256>>>(Q);
    k_prep_x<<<(BDIM * NDIM / 16) / 256, 256>>>(x);
    k_prep_q<<<(NDIM * NDIM / 16) / 256, 256>>>(Q);
    k_gemm<<<dim3(NT, MT), 256, SMEM_BYTES>>>(x);
    k_finish<<<BDIM / 256, 256>>>(out);
}

// round 4
// speedup vs baseline: 1.0049x; 1.0049x over previous
#include <cuda_runtime.h>
#include <cuda_bf16.h>
#include <cstdint>

// ============================================================================
// BinaryToCost: out[i] = x_i @ Q @ x_i  (x: 1024x2048 {0,1} fp32, Q: 2048^2 fp32)
// Two-level int8 quantized IMMA GEMM:  Q ≈ s*q_hi + (s/254)*q_lo  (s8 each),
// exact int32 accumulation, deterministic integer atomics, scale at the end.
// Uses x^T Q x == x^T Q^T x  => no transpose needed for the B operand.
// ============================================================================

#define NDIM 2048
#define BDIM 1024
#define BM 128
#define BN 128
#define NCHUNK 32          // 16 chunks (k=128 int8) for q_hi + 16 for q_lo
#define NT (NDIM / BN)     // 16
#define MT (BDIM / BM)     // 8
#define STAGE_BYTES 32768  // A(16KB int8) + B(16KB int8)
#define SMEM_BYTES (2 * STAGE_BYTES)

// ---------------------------------------------------------------------------
__device__ __align__(16) int8_t g_xi[BDIM * NDIM];   // 2 MB  x as s8 {0,1}
__device__ __align__(16) int8_t g_qh[NDIM * NDIM];   // 4 MB  hi-level s8 of Q
__device__ __align__(16) int8_t g_ql[NDIM * NDIM];   // 4 MB  lo-level s8 of Q
__device__ int g_acc_hi[BDIM];
__device__ int g_acc_lo[BDIM];
__device__ unsigned g_maxbits;

// ---------------------------------------------------------------------------
__device__ __forceinline__ uint32_t smem_u32(const void* p) {
    return (uint32_t)__cvta_generic_to_shared(p);
}
__device__ __forceinline__ uint32_t sw128(uint32_t off) {
    return off ^ ((off >> 3) & 0x70);
}
__device__ __forceinline__ void cp_async16(uint32_t dst, const void* src) {
    asm volatile("cp.async.cg.shared.global [%0], [%1], 16;"
                 :: "r"(dst), "l"(src) : "memory");
}

#define LDSM_X4(r, addr)                                                      \
    asm volatile("ldmatrix.sync.aligned.m8n8.x4.shared.b16 {%0,%1,%2,%3}, [%4];" \
                 : "=r"((r)[0]), "=r"((r)[1]), "=r"((r)[2]), "=r"((r)[3])     \
                 : "r"(addr))

__device__ __forceinline__ void imma16832(int* d, const uint32_t* a,
                                          const uint32_t* b) {
    asm volatile(
        "mma.sync.aligned.m16n8k32.row.col.s32.s8.s8.s32 "
        "{%0,%1,%2,%3}, {%4,%5,%6,%7}, {%8,%9}, {%0,%1,%2,%3};"
        : "+r"(d[0]), "+r"(d[1]), "+r"(d[2]), "+r"(d[3])
        : "r"(a[0]), "r"(a[1]), "r"(a[2]), "r"(a[3]), "r"(b[0]), "r"(b[1]));
}

__device__ __forceinline__ uint32_t pack4(int a, int b, int c, int d) {
    return (a & 0xff) | ((b & 0xff) << 8) | ((c & 0xff) << 16) |
           ((unsigned)(d & 0xff) << 24);
}

// ---------------------------------------------------------------------------
// Prep kernels
// ---------------------------------------------------------------------------
__global__ void k_zero() {
    int t = threadIdx.x;
    g_acc_hi[t] = 0;
    g_acc_lo[t] = 0;
    if (t == 0) g_maxbits = 0;
}

// max|Q| via bit-pattern atomicMax (monotone for abs-float); deterministic.
__global__ void k_max(const float* __restrict__ Q) {
    const float4* q4 = reinterpret_cast<const float4*>(Q);
    int i = blockIdx.x * blockDim.x + threadIdx.x;
    unsigned mx = 0;
#pragma unroll
    for (int j = 0; j < 4; ++j) {
        float4 v = q4[i + j * 262144];
        mx = max(mx, __float_as_uint(v.x) & 0x7fffffffu);
        mx = max(mx, __float_as_uint(v.y) & 0x7fffffffu);
        mx = max(mx, __float_as_uint(v.z) & 0x7fffffffu);
        mx = max(mx, __float_as_uint(v.w) & 0x7fffffffu);
    }
#pragma unroll
    for (int o = 16; o > 0; o >>= 1)
        mx = max(mx, __shfl_xor_sync(0xFFFFFFFF, mx, o));
    if ((threadIdx.x & 31) == 0) atomicMax(&g_maxbits, mx);
}

__global__ void k_prep_x(const float* __restrict__ x) {
    int i = blockIdx.x * blockDim.x + threadIdx.x;  // 16 elems / thread
    const float4* x4 = reinterpret_cast<const float4*>(x) + i * 4;
    uint32_t w[4];
#pragma unroll
    for (int j = 0; j < 4; ++j) {
        float4 v = x4[j];
        w[j] = pack4(v.x != 0.0f, v.y != 0.0f, v.z != 0.0f, v.w != 0.0f);
    }
    reinterpret_cast<uint4*>(g_xi)[i] = make_uint4(w[0], w[1], w[2], w[3]);
}

// Two-level s8 quantization of Q (no transpose needed).
__global__ void k_prep_q(const float* __restrict__ Q) {
    const float maxv = __uint_as_float(g_maxbits);
    const float s = maxv * (1.0f / 127.0f);
    const float s2 = s * (1.0f / 254.0f);
    const float inv_s = 127.0f / maxv;
    const float inv_s2 = inv_s * 254.0f;

    int i = blockIdx.x * blockDim.x + threadIdx.x;  // 16 elems / thread
    const float4* q4 = reinterpret_cast<const float4*>(Q) + i * 4;
    int hi[16], lo[16];
#pragma unroll
    for (int j = 0; j < 4; ++j) {
        float4 v = q4[j];
        float vv[4] = {v.x, v.y, v.z, v.w};
#pragma unroll
        for (int e = 0; e < 4; ++e) {
            int qh = __float2int_rn(vv[e] * inv_s);
            float r = fmaf((float)-qh, s, vv[e]);
            int ql = __float2int_rn(r * inv_s2);
            hi[j * 4 + e] = qh;
            lo[j * 4 + e] = ql;
        }
    }
    uint4 ph = make_uint4(pack4(hi[0], hi[1], hi[2], hi[3]),
                          pack4(hi[4], hi[5], hi[6], hi[7]),
                          pack4(hi[8], hi[9], hi[10], hi[11]),
                          pack4(hi[12], hi[13], hi[14], hi[15]));
    uint4 pl = make_uint4(pack4(lo[0], lo[1], lo[2], lo[3]),
                          pack4(lo[4], lo[5], lo[6], lo[7]),
                          pack4(lo[8], lo[9], lo[10], lo[11]),
                          pack4(lo[12], lo[13], lo[14], lo[15]));
    reinterpret_cast<uint4*>(g_qh)[i] = ph;
    reinterpret_cast<uint4*>(g_ql)[i] = pl;
}

// ---------------------------------------------------------------------------
// int8 GEMM + fused masked row-reduce.  grid (NT, MT), 256 threads (8 warps).
// Warp tile 64x32 (warps 2M x 4N), per warp 4 m16 x 4 n8 imma tiles, k=32/mma.
// Chunks of k=128 bytes; chunks 0-15 = q_hi, 16-31 = q_lo, int32 accumulators
// folded (with per-row/col x mask) into integer row sums at pass boundaries.
// ---------------------------------------------------------------------------
__global__ void __launch_bounds__(256, 1)
k_gemm(const float* __restrict__ x) {
    extern __shared__ __align__(1024) uint8_t smem[];

    const int tid = threadIdx.x;
    const int wid = tid >> 5;
    const int lane = tid & 31;
    const int n0 = blockIdx.x * BN;
    const int m0 = blockIdx.y * BM;
    const int wm = (wid >> 2) * 64;
    const int wn = (wid & 3) * 32;
    const int grp = lane >> 3;
    const int ri = lane & 7;

    // cp.async staging: 1024 16B-granules per 16KB tile, 4/thread per operand
    int rr[4], cc[4];
#pragma unroll
    for (int i = 0; i < 4; ++i) {
        int g = tid + 256 * i;
        rr[i] = g >> 3;
        cc[i] = g & 7;
    }

    auto stage_load = [&](int c, int buf) {
        uint32_t sa = smem_u32(smem + buf * STAGE_BYTES);
        uint32_t sb = sa + 16384;
        int kb = (c & 15) * 128;
        const int8_t* qs = (c < 16) ? g_qh : g_ql;
#pragma unroll
        for (int i = 0; i < 4; ++i) {
            uint32_t off = sw128((uint32_t)(rr[i] * 128 + cc[i] * 16));
            cp_async16(sa + off, g_xi + (m0 + rr[i]) * NDIM + kb + cc[i] * 16);
            cp_async16(sb + off, qs + (n0 + rr[i]) * NDIM + kb + cc[i] * 16);
        }
        asm volatile("cp.async.commit_group;" ::: "memory");
    };

    int cfrag[4][4][4];
#pragma unroll
    for (int mt = 0; mt < 4; ++mt)
#pragma unroll
        for (int nt = 0; nt < 4; ++nt)
#pragma unroll
            for (int r = 0; r < 4; ++r) cfrag[mt][nt][r] = 0;

    int rs_hi0[4] = {0, 0, 0, 0}, rs_hi1[4] = {0, 0, 0, 0};
    int rs_lo0[4] = {0, 0, 0, 0}, rs_lo1[4] = {0, 0, 0, 0};

    // Fold cfrag into masked int row sums, then clear cfrag.
    auto fold = [&](int* r0s, int* r1s) {
#pragma unroll
        for (int mt = 0; mt < 4; ++mt) {
            const float* xp0 =
                x + (m0 + wm + mt * 16 + (lane >> 2)) * NDIM + n0 + wn + (lane & 3) * 2;
            const float* xp1 = xp0 + 8 * NDIM;
            int a0 = 0, a1 = 0;
#pragma unroll
            for (int nt = 0; nt < 4; ++nt) {
                float2 v0 = *reinterpret_cast<const float2*>(xp0 + nt * 8);
                float2 v1 = *reinterpret_cast<const float2*>(xp1 + nt * 8);
                if (v0.x != 0.0f) a0 += cfrag[mt][nt][0];
                if (v0.y != 0.0f) a0 += cfrag[mt][nt][1];
                if (v1.x != 0.0f) a1 += cfrag[mt][nt][2];
                if (v1.y != 0.0f) a1 += cfrag[mt][nt][3];
#pragma unroll
                for (int r = 0; r < 4; ++r) cfrag[mt][nt][r] = 0;
            }
            r0s[mt] += a0;
            r1s[mt] += a1;
        }
    };

    stage_load(0, 0);
    stage_load(1, 1);

    for (int ch = 0; ch < NCHUNK; ++ch) {
        if (ch == NCHUNK - 1)
            asm volatile("cp.async.wait_group 0;" ::: "memory");
        else
            asm volatile("cp.async.wait_group 1;" ::: "memory");
        __syncthreads();

        const int buf = ch & 1;
        const uint32_t sa = smem_u32(smem + buf * STAGE_BYTES);
        const uint32_t sb = sa + 16384;

#pragma unroll
        for (int s = 0; s < 4; ++s) {   // 4 k32-steps per 128B chunk
            const int kb = s * 32;      // byte offset within row
            uint32_t a[4][4];
#pragma unroll
            for (int mt = 0; mt < 4; ++mt) {
                int row = wm + mt * 16 + (grp & 1) * 8 + ri;
                uint32_t addr = sa + sw128((uint32_t)(row * 128 + kb + (grp >> 1) * 16));
                LDSM_X4(a[mt], addr);
            }
            uint32_t b[2][4];
#pragma unroll
            for (int nt2 = 0; nt2 < 2; ++nt2) {
                int row = wn + nt2 * 16 + (grp >> 1) * 8 + ri;
                uint32_t addr = sb + sw128((uint32_t)(row * 128 + kb + (grp & 1) * 16));
                LDSM_X4(b[nt2], addr);
            }
#pragma unroll
            for (int mt = 0; mt < 4; ++mt)
#pragma unroll
                for (int nt = 0; nt < 4; ++nt)
                    imma16832(cfrag[mt][nt], a[mt], &b[nt >> 1][(nt & 1) * 2]);
        }

        __syncthreads();
        if (ch + 2 < NCHUNK) stage_load(ch + 2, buf);

        if (ch == 15) fold(rs_hi0, rs_hi1);
        if (ch == NCHUNK - 1) fold(rs_lo0, rs_lo1);
    }

    // Reduce across the 4 lanes of each row group; leaders atomically add
    // (integer atomics: exact & order-independent => deterministic).
#pragma unroll
    for (int mt = 0; mt < 4; ++mt) {
#pragma unroll
        for (int o = 1; o <= 2; o <<= 1) {
            rs_hi0[mt] += __shfl_xor_sync(0xFFFFFFFF, rs_hi0[mt], o);
            rs_hi1[mt] += __shfl_xor_sync(0xFFFFFFFF, rs_hi1[mt], o);
            rs_lo0[mt] += __shfl_xor_sync(0xFFFFFFFF, rs_lo0[mt], o);
            rs_lo1[mt] += __shfl_xor_sync(0xFFFFFFFF, rs_lo1[mt], o);
        }
    }
    if ((lane & 3) == 0) {
#pragma unroll
        for (int mt = 0; mt < 4; ++mt) {
            int row = m0 + wm + mt * 16 + (lane >> 2);
            atomicAdd(&g_acc_hi[row], rs_hi0[mt]);
            atomicAdd(&g_acc_hi[row + 8], rs_hi1[mt]);
            atomicAdd(&g_acc_lo[row], rs_lo0[mt]);
            atomicAdd(&g_acc_lo[row + 8], rs_lo1[mt]);
        }
    }
}

// Apply scales: out = s*hi + (s/254)*lo
__global__ void k_finish(float* __restrict__ out) {
    const float maxv = __uint_as_float(g_maxbits);
    const float s = maxv * (1.0f / 127.0f);
    const float s2 = s * (1.0f / 254.0f);
    int m = blockIdx.x * blockDim.x + threadIdx.x;
    out[m] = s * (float)g_acc_hi[m] + s2 * (float)g_acc_lo[m];
}

// ---------------------------------------------------------------------------
extern "C" void kernel_launch(void* const* d_in, const int* in_sizes, int n_in,
                              void* d_out, int out_size) {
    const float* x = (const float*)d_in[0];  // [1024, 2048]
    const float* Q = (const float*)d_in[1];  // [2048, 2048]
    float* out = (float*)d_out;              // [1024]

    static bool attr_set = false;
    if (!attr_set) {
        cudaFuncSetAttribute(k_gemm, cudaFuncAttributeMaxDynamicSharedMemorySize,
                             SMEM_BYTES);
        attr_set = true;
    }

    k_zero<<<1, BDIM>>>();
    k_max<<<1024, 256>>>(Q);
    k_prep_x<<<(BDIM * NDIM / 16) / 256, 256>>>(x);
    k_prep_q<<<(NDIM * NDIM / 16) / 256, 256>>>(Q);
    k_gemm<<<dim3(NT, MT), 256, SMEM_BYTES>>>(x);
    k_finish<<<BDIM / 256, 256>>>(out);
}

// round 5
// speedup vs baseline: 2.2664x; 2.2555x over previous
#include <cuda_runtime.h>
#include <cuda_bf16.h>
#include <cstdint>

// ============================================================================
// BinaryToCost: out[i] = x_i @ Q @ x_i  (x: 1024x2048 {0,1} fp32, Q: 2048^2 fp32)
// Split-precision bf16 mma.sync GEMM (Q = Qhi + Qlo), fused masked row-reduce,
// 4-stage cp.async pipeline, last-CTA final reduction (2 launches total).
// ============================================================================

#define NDIM 2048
#define BDIM 1024
#define BM 128
#define BN 128
#define BK 64              // K elems per chunk (128B rows, SW128 atom)
#define NCHUNK 64          // 32 chunks Qhi + 32 chunks Qlo
#define NT (NDIM / BN)     // 16
#define MT (BDIM / BM)     // 8
#define NSTAGE 4
#define STAGE_BYTES 32768  // A(16KB) + B(16KB)
#define SMEM_BYTES (NSTAGE * STAGE_BYTES)

// ---------------------------------------------------------------------------
__device__ __align__(16) __nv_bfloat16 g_xh[BDIM * NDIM];    // bf16(x)      [m][k]
__device__ __align__(16) __nv_bfloat16 g_qhiT[NDIM * NDIM];  // bf16(Q)^T    [n][k]
__device__ __align__(16) __nv_bfloat16 g_qloT[NDIM * NDIM];  // bf16 resid^T [n][k]
__device__ float g_partial[NT * BDIM];
__device__ unsigned g_cnt = 0;

// ---------------------------------------------------------------------------
__device__ __forceinline__ uint32_t smem_u32(const void* p) {
    return (uint32_t)__cvta_generic_to_shared(p);
}
__device__ __forceinline__ uint32_t sw128(uint32_t off) {
    return off ^ ((off >> 3) & 0x70);
}
__device__ __forceinline__ void cp_async16(uint32_t dst, const void* src) {
    asm volatile("cp.async.cg.shared.global [%0], [%1], 16;"
                 :: "r"(dst), "l"(src) : "memory");
}

#define LDSM_X4(r, addr)                                                      \
    asm volatile("ldmatrix.sync.aligned.m8n8.x4.shared.b16 {%0,%1,%2,%3}, [%4];" \
                 : "=r"((r)[0]), "=r"((r)[1]), "=r"((r)[2]), "=r"((r)[3])     \
                 : "r"(addr))

__device__ __forceinline__ void mma16816(float* d, const uint32_t* a,
                                         const uint32_t* b) {
    asm volatile(
        "mma.sync.aligned.m16n8k16.row.col.f32.bf16.bf16.f32 "
        "{%0,%1,%2,%3}, {%4,%5,%6,%7}, {%8,%9}, {%0,%1,%2,%3};"
        : "+f"(d[0]), "+f"(d[1]), "+f"(d[2]), "+f"(d[3])
        : "r"(a[0]), "r"(a[1]), "r"(a[2]), "r"(a[3]), "r"(b[0]), "r"(b[1]));
}

// ---------------------------------------------------------------------------
// Fused prep: blocks [0, 4096) transpose+split Q; blocks [4096, 6144) pack x.
// ---------------------------------------------------------------------------
__global__ void __launch_bounds__(256)
k_prep(const float* __restrict__ x, const float* __restrict__ Q) {
    __shared__ float tile[32][33];
    const int b = blockIdx.x;
    if (b < 4096) {
        int bx = (b & 63) * 32;  // n base
        int by = (b >> 6) * 32;  // k base
        int tx = threadIdx.x & 31, ty = threadIdx.x >> 5;  // 32 x 8
#pragma unroll
        for (int i = 0; i < 32; i += 8)
            tile[ty + i][tx] = Q[(by + ty + i) * NDIM + bx + tx];
        __syncthreads();
#pragma unroll
        for (int i = 0; i < 32; i += 8) {
            float v = tile[tx][ty + i];
            __nv_bfloat16 h = __float2bfloat16(v);
            float lo = v - __bfloat162float(h);
            int n = bx + ty + i;
            int k = by + tx;
            g_qhiT[n * NDIM + k] = h;
            g_qloT[n * NDIM + k] = __float2bfloat16(lo);
        }
    } else {
        int i = (b - 4096) * 256 + threadIdx.x;  // float4 index over x
        float4 v = reinterpret_cast<const float4*>(x)[i];
        __nv_bfloat162* o = reinterpret_cast<__nv_bfloat162*>(g_xh);
        o[2 * i + 0] = __floats2bfloat162_rn(v.x, v.y);
        o[2 * i + 1] = __floats2bfloat162_rn(v.z, v.w);
    }
}

// ---------------------------------------------------------------------------
// GEMM + fused masked row-reduce + last-CTA final reduction.
// grid (NT, MT), 256 threads (8 warps, 2M x 4N, warp tile 64x32).
// ---------------------------------------------------------------------------
__global__ void __launch_bounds__(256, 1)
k_gemm(const float* __restrict__ x, float* __restrict__ out) {
    extern __shared__ __align__(1024) uint8_t smem[];

    const int tid = threadIdx.x;
    const int wid = tid >> 5;
    const int lane = tid & 31;
    const int n0 = blockIdx.x * BN;
    const int m0 = blockIdx.y * BM;
    const int wm = (wid >> 2) * 64;
    const int wn = (wid & 3) * 32;
    const int grp = lane >> 3;
    const int ri = lane & 7;

    // cp.async staging map: 1024 16B-granules per 16KB tile, 4/thread/operand
    int rr[4], cc[4];
#pragma unroll
    for (int i = 0; i < 4; ++i) {
        int g = tid + 256 * i;
        rr[i] = g >> 3;
        cc[i] = g & 7;
    }

    auto stage_load = [&](int c) {
        uint32_t sa = smem_u32(smem + (c % NSTAGE) * STAGE_BYTES);
        uint32_t sb = sa + 16384;
        int kbE = (c & 31) * BK;
        const __nv_bfloat16* qs = (c < 32) ? g_qhiT : g_qloT;
#pragma unroll
        for (int i = 0; i < 4; ++i) {
            uint32_t off = sw128((uint32_t)(rr[i] * 128 + cc[i] * 16));
            cp_async16(sa + off, g_xh + (m0 + rr[i]) * NDIM + kbE + cc[i] * 8);
            cp_async16(sb + off, qs + (n0 + rr[i]) * NDIM + kbE + cc[i] * 8);
        }
        asm volatile("cp.async.commit_group;" ::: "memory");
    };

    float cfrag[4][4][4];
#pragma unroll
    for (int mt = 0; mt < 4; ++mt)
#pragma unroll
        for (int nt = 0; nt < 4; ++nt)
#pragma unroll
            for (int r = 0; r < 4; ++r) cfrag[mt][nt][r] = 0.0f;

    stage_load(0);
    stage_load(1);
    stage_load(2);

    for (int ch = 0; ch < NCHUNK; ++ch) {
        if (ch < NCHUNK - 2)
            asm volatile("cp.async.wait_group 2;" ::: "memory");
        else if (ch == NCHUNK - 2)
            asm volatile("cp.async.wait_group 1;" ::: "memory");
        else
            asm volatile("cp.async.wait_group 0;" ::: "memory");
        __syncthreads();

        // issue next stage ASAP: target buffer was last read in iter ch-1
        if (ch + NSTAGE - 1 < NCHUNK) stage_load(ch + NSTAGE - 1);

        const uint32_t sa = smem_u32(smem + (ch % NSTAGE) * STAGE_BYTES);
        const uint32_t sb = sa + 16384;

#pragma unroll
        for (int s = 0; s < 4; ++s) {  // 4 k16-steps per chunk
            const int kb = s * 32;     // byte offset within 128B row
            uint32_t a[4][4];
#pragma unroll
            for (int mt = 0; mt < 4; ++mt) {
                int row = wm + mt * 16 + (grp & 1) * 8 + ri;
                uint32_t addr = sa + sw128((uint32_t)(row * 128 + kb + (grp >> 1) * 16));
                LDSM_X4(a[mt], addr);
            }
            uint32_t b[2][4];
#pragma unroll
            for (int nt2 = 0; nt2 < 2; ++nt2) {
                int row = wn + nt2 * 16 + (grp >> 1) * 8 + ri;
                uint32_t addr = sb + sw128((uint32_t)(row * 128 + kb + (grp & 1) * 16));
                LDSM_X4(b[nt2], addr);
            }
#pragma unroll
            for (int mt = 0; mt < 4; ++mt)
#pragma unroll
                for (int nt = 0; nt < 4; ++nt)
                    mma16816(cfrag[mt][nt], a[mt], &b[nt >> 1][(nt & 1) * 2]);
        }
    }

    // ---- Epilogue: masked row sums (deterministic) ----
    float acc0[4], acc1[4];
#pragma unroll
    for (int mt = 0; mt < 4; ++mt) {
        float a0 = 0.0f, a1 = 0.0f;
        const int r0 = m0 + wm + mt * 16 + (lane >> 2);
#pragma unroll
        for (int nt = 0; nt < 4; ++nt) {
            const int ng = n0 + wn + nt * 8 + (lane & 3) * 2;
            const float* x0 = x + r0 * NDIM + ng;
            const float* x1 = x0 + 8 * NDIM;
            a0 += cfrag[mt][nt][0] * x0[0] + cfrag[mt][nt][1] * x0[1];
            a1 += cfrag[mt][nt][2] * x1[0] + cfrag[mt][nt][3] * x1[1];
        }
        a0 += __shfl_xor_sync(0xFFFFFFFF, a0, 1);
        a0 += __shfl_xor_sync(0xFFFFFFFF, a0, 2);
        a1 += __shfl_xor_sync(0xFFFFFFFF, a1, 1);
        a1 += __shfl_xor_sync(0xFFFFFFFF, a1, 2);
        acc0[mt] = a0;
        acc1[mt] = a1;
    }

    __syncthreads();  // smem stages free; reuse for cross-warp reduction
    float* red = reinterpret_cast<float*>(smem);  // [4 n-groups][128 rows]
    if ((lane & 3) == 0) {
        const int ng = wid & 3;
#pragma unroll
        for (int mt = 0; mt < 4; ++mt) {
            int row = wm + mt * 16 + (lane >> 2);
            red[ng * 128 + row] = acc0[mt];
            red[ng * 128 + row + 8] = acc1[mt];
        }
    }
    __syncthreads();
    if (tid < 128) {
        float p = red[tid] + red[128 + tid] + red[256 + tid] + red[384 + tid];
        g_partial[blockIdx.x * BDIM + m0 + tid] = p;
    }

    // ---- Last-CTA final reduction (threadfence-reduction pattern) ----
    __shared__ unsigned s_old;
    __syncthreads();
    if (tid == 0) {
        __threadfence();
        s_old = atomicAdd(&g_cnt, 1u);
    }
    __syncthreads();
    if (s_old == NT * MT - 1) {
        __threadfence();
        for (int m = tid; m < BDIM; m += 256) {
            float s = 0.0f;
#pragma unroll
            for (int nt = 0; nt < NT; ++nt) s += g_partial[nt * BDIM + m];
            out[m] = s;
        }
        if (tid == 0) g_cnt = 0;  // reset for next graph replay
    }
}

// ---------------------------------------------------------------------------
extern "C" void kernel_launch(void* const* d_in, const int* in_sizes, int n_in,
                              void* d_out, int out_size) {
    const float* x = (const float*)d_in[0];  // [1024, 2048]
    const float* Q = (const float*)d_in[1];  // [2048, 2048]
    float* out = (float*)d_out;              // [1024]

    static bool attr_set = false;
    if (!attr_set) {
        cudaFuncSetAttribute(k_gemm, cudaFuncAttributeMaxDynamicSharedMemorySize,
                             SMEM_BYTES);
        attr_set = true;
    }

    k_prep<<<4096 + (BDIM * NDIM / 4) / 256, 256>>>(x, Q);
    k_gemm<<<dim3(NT, MT), 256, SMEM_BYTES>>>(x, out);
}

// round 6
// speedup vs baseline: 2.5438x; 1.1224x over previous
#include <cuda_runtime.h>
#include <cuda_bf16.h>
#include <cstdint>

// ============================================================================
// BinaryToCost: out[i] = x_i @ Q @ x_i  (x: 1024x2048 {0,1} fp32, Q: 2048^2 fp32)
// Split-precision bf16 mma.sync GEMM (Q = Qhi + Qlo), split-K across 2 passes
// (grid z), 2 CTAs/SM, fused masked row-reduce, last-CTA final reduction.
// Symmetry trick: B operand reads row-major Q directly (x Q^T x == x Q x).
// ============================================================================

#define NDIM 2048
#define BDIM 1024
#define BM 128
#define BN 128
#define BK 64              // K elems per chunk (128B rows, SW128 atom)
#define NCHUNK 32          // chunks per CTA (one pass of K)
#define NT (NDIM / BN)     // 16
#define MT (BDIM / BM)     // 8
#define NCTA (NT * MT * 2) // 256
#define NSTAGE 3
#define STAGE_BYTES 32768  // A(16KB) + B(16KB)
#define SMEM_BYTES (NSTAGE * STAGE_BYTES)

// ---------------------------------------------------------------------------
__device__ __align__(16) __nv_bfloat16 g_xh[BDIM * NDIM];   // bf16(x)    [m][k]
__device__ __align__(16) __nv_bfloat16 g_qhi[NDIM * NDIM];  // bf16(Q)    row-major
__device__ __align__(16) __nv_bfloat16 g_qlo[NDIM * NDIM];  // bf16 resid row-major
__device__ float g_partial[2 * NT * BDIM];
__device__ unsigned g_cnt = 0;

// ---------------------------------------------------------------------------
__device__ __forceinline__ uint32_t smem_u32(const void* p) {
    return (uint32_t)__cvta_generic_to_shared(p);
}
__device__ __forceinline__ uint32_t sw128(uint32_t off) {
    return off ^ ((off >> 3) & 0x70);
}
__device__ __forceinline__ void cp_async16(uint32_t dst, const void* src) {
    asm volatile("cp.async.cg.shared.global [%0], [%1], 16;"
                 :: "r"(dst), "l"(src) : "memory");
}

#define LDSM_X4(r, addr)                                                      \
    asm volatile("ldmatrix.sync.aligned.m8n8.x4.shared.b16 {%0,%1,%2,%3}, [%4];" \
                 : "=r"((r)[0]), "=r"((r)[1]), "=r"((r)[2]), "=r"((r)[3])     \
                 : "r"(addr))

__device__ __forceinline__ void mma16816(float* d, const uint32_t* a,
                                         const uint32_t* b) {
    asm volatile(
        "mma.sync.aligned.m16n8k16.row.col.f32.bf16.bf16.f32 "
        "{%0,%1,%2,%3}, {%4,%5,%6,%7}, {%8,%9}, {%0,%1,%2,%3};"
        : "+f"(d[0]), "+f"(d[1]), "+f"(d[2]), "+f"(d[3])
        : "r"(a[0]), "r"(a[1]), "r"(a[2]), "r"(a[3]), "r"(b[0]), "r"(b[1]));
}

// ---------------------------------------------------------------------------
// Streaming prep (no transpose needed): blocks [0,2048) split Q, rest pack x.
// 8 elements per thread, fully coalesced.
// ---------------------------------------------------------------------------
__global__ void __launch_bounds__(256)
k_prep(const float* __restrict__ x, const float* __restrict__ Q) {
    const int b = blockIdx.x;
    if (b < 2048) {
        int i = b * 256 + threadIdx.x;  // 8-elem group index over Q
        const float4* q4 = reinterpret_cast<const float4*>(Q) + i * 2;
        float4 v0 = q4[0], v1 = q4[1];
        float vv[8] = {v0.x, v0.y, v0.z, v0.w, v1.x, v1.y, v1.z, v1.w};
        __nv_bfloat16 h[8], l[8];
#pragma unroll
        for (int e = 0; e < 8; ++e) {
            h[e] = __float2bfloat16(vv[e]);
            l[e] = __float2bfloat16(vv[e] - __bfloat162float(h[e]));
        }
        reinterpret_cast<uint4*>(g_qhi)[i] = *reinterpret_cast<uint4*>(h);
        reinterpret_cast<uint4*>(g_qlo)[i] = *reinterpret_cast<uint4*>(l);
    } else {
        int i = (b - 2048) * 256 + threadIdx.x;  // 8-elem group index over x
        const float4* x4 = reinterpret_cast<const float4*>(x) + i * 2;
        float4 v0 = x4[0], v1 = x4[1];
        __nv_bfloat162 p[4];
        p[0] = __floats2bfloat162_rn(v0.x, v0.y);
        p[1] = __floats2bfloat162_rn(v0.z, v0.w);
        p[2] = __floats2bfloat162_rn(v1.x, v1.y);
        p[3] = __floats2bfloat162_rn(v1.z, v1.w);
        reinterpret_cast<uint4*>(g_xh)[i] = *reinterpret_cast<uint4*>(p);
    }
}

// ---------------------------------------------------------------------------
// GEMM + fused masked row-reduce + last-CTA final reduction.
// grid (NT, MT, 2): z=0 -> Qhi pass, z=1 -> Qlo pass. 256 threads, 2 CTAs/SM.
// Warp layout 2M x 4N, warp tile 64x32.
// ---------------------------------------------------------------------------
__global__ void __launch_bounds__(256, 2)
k_gemm(const float* __restrict__ x, float* __restrict__ out) {
    extern __shared__ __align__(1024) uint8_t smem[];

    const int tid = threadIdx.x;
    const int wid = tid >> 5;
    const int lane = tid & 31;
    const int n0 = blockIdx.x * BN;
    const int m0 = blockIdx.y * BM;
    const int wm = (wid >> 2) * 64;
    const int wn = (wid & 3) * 32;
    const int grp = lane >> 3;
    const int ri = lane & 7;
    const __nv_bfloat16* __restrict__ qs = blockIdx.z ? g_qlo : g_qhi;

    auto stage_load = [&](int c) {
        uint32_t sa = smem_u32(smem) + (c % NSTAGE) * STAGE_BYTES;
        uint32_t sb = sa + 16384;
        int kbE = c * BK;
#pragma unroll
        for (int i = 0; i < 4; ++i) {
            int g = tid + 256 * i;
            int rr = g >> 3;
            int cc = g & 7;
            uint32_t off = sw128((uint32_t)(rr * 128 + cc * 16));
            cp_async16(sa + off, g_xh + (m0 + rr) * NDIM + kbE + cc * 8);
            cp_async16(sb + off, qs + (n0 + rr) * NDIM + kbE + cc * 8);
        }
        asm volatile("cp.async.commit_group;" ::: "memory");
    };

    float cfrag[4][4][4];
#pragma unroll
    for (int mt = 0; mt < 4; ++mt)
#pragma unroll
        for (int nt = 0; nt < 4; ++nt)
#pragma unroll
            for (int r = 0; r < 4; ++r) cfrag[mt][nt][r] = 0.0f;

    stage_load(0);
    stage_load(1);

    for (int ch = 0; ch < NCHUNK; ++ch) {
        if (ch < NCHUNK - 1)
            asm volatile("cp.async.wait_group 1;" ::: "memory");
        else
            asm volatile("cp.async.wait_group 0;" ::: "memory");
        __syncthreads();

        if (ch + 2 < NCHUNK) stage_load(ch + 2);

        const uint32_t sa = smem_u32(smem) + (ch % NSTAGE) * STAGE_BYTES;
        const uint32_t sb = sa + 16384;

#pragma unroll
        for (int s = 0; s < 4; ++s) {  // 4 k16-steps per chunk
            const int kb = s * 32;
            uint32_t a[4][4];
#pragma unroll
            for (int mt = 0; mt < 4; ++mt) {
                int row = wm + mt * 16 + (grp & 1) * 8 + ri;
                uint32_t addr = sa + sw128((uint32_t)(row * 128 + kb + (grp >> 1) * 16));
                LDSM_X4(a[mt], addr);
            }
            uint32_t b[2][4];
#pragma unroll
            for (int nt2 = 0; nt2 < 2; ++nt2) {
                int row = wn + nt2 * 16 + (grp >> 1) * 8 + ri;
                uint32_t addr = sb + sw128((uint32_t)(row * 128 + kb + (grp & 1) * 16));
                LDSM_X4(b[nt2], addr);
            }
#pragma unroll
            for (int mt = 0; mt < 4; ++mt)
#pragma unroll
                for (int nt = 0; nt < 4; ++nt)
                    mma16816(cfrag[mt][nt], a[mt], &b[nt >> 1][(nt & 1) * 2]);
        }
    }

    // ---- Epilogue: masked row sums (deterministic) ----
    float acc0[4], acc1[4];
#pragma unroll
    for (int mt = 0; mt < 4; ++mt) {
        float a0 = 0.0f, a1 = 0.0f;
        const int r0 = m0 + wm + mt * 16 + (lane >> 2);
#pragma unroll
        for (int nt = 0; nt < 4; ++nt) {
            const int ng = n0 + wn + nt * 8 + (lane & 3) * 2;
            const float* x0 = x + r0 * NDIM + ng;
            const float* x1 = x0 + 8 * NDIM;
            a0 += cfrag[mt][nt][0] * x0[0] + cfrag[mt][nt][1] * x0[1];
            a1 += cfrag[mt][nt][2] * x1[0] + cfrag[mt][nt][3] * x1[1];
        }
        a0 += __shfl_xor_sync(0xFFFFFFFF, a0, 1);
        a0 += __shfl_xor_sync(0xFFFFFFFF, a0, 2);
        a1 += __shfl_xor_sync(0xFFFFFFFF, a1, 1);
        a1 += __shfl_xor_sync(0xFFFFFFFF, a1, 2);
        acc0[mt] = a0;
        acc1[mt] = a1;
    }

    __syncthreads();  // stage smem free; reuse for cross-warp reduction
    float* red = reinterpret_cast<float*>(smem);  // [4 n-groups][128 rows]
    if ((lane & 3) == 0) {
        const int ng = wid & 3;
#pragma unroll
        for (int mt = 0; mt < 4; ++mt) {
            int row = wm + mt * 16 + (lane >> 2);
            red[ng * 128 + row] = acc0[mt];
            red[ng * 128 + row + 8] = acc1[mt];
        }
    }
    __syncthreads();
    if (tid < 128) {
        float p = red[tid] + red[128 + tid] + red[256 + tid] + red[384 + tid];
        g_partial[(blockIdx.z * NT + blockIdx.x) * BDIM + m0 + tid] = p;
    }

    // ---- Last-CTA final reduction ----
    __shared__ unsigned s_old;
    __syncthreads();
    if (tid == 0) {
        __threadfence();
        s_old = atomicAdd(&g_cnt, 1u);
    }
    __syncthreads();
    if (s_old == NCTA - 1) {
        __threadfence();
        for (int m = tid; m < BDIM; m += 256) {
            float s = 0.0f;
#pragma unroll
            for (int p = 0; p < 2 * NT; ++p) s += g_partial[p * BDIM + m];
            out[m] = s;
        }
        if (tid == 0) g_cnt = 0;  // reset for next graph replay
    }
}

// ---------------------------------------------------------------------------
extern "C" void kernel_launch(void* const* d_in, const int* in_sizes, int n_in,
                              void* d_out, int out_size) {
    const float* x = (const float*)d_in[0];  // [1024, 2048]
    const float* Q = (const float*)d_in[1];  // [2048, 2048]
    float* out = (float*)d_out;              // [1024]

    static bool attr_set = false;
    if (!attr_set) {
        cudaFuncSetAttribute(k_gemm, cudaFuncAttributeMaxDynamicSharedMemorySize,
                             SMEM_BYTES);
        attr_set = true;
    }

    k_prep<<<2048 + 1024, 256>>>(x, Q);
    k_gemm<<<dim3(NT, MT, 2), 256, SMEM_BYTES>>>(x, out);
}